// round 1
// baseline (speedup 1.0000x reference)
#include <cuda_runtime.h>
#include <math.h>

// Problem constants (B=4, T=2048, D=1024, FF=4096, E=8, K=2)
#define N_TOK   8192
#define K_TOP   2
#define NE      8
#define D_MODEL 1024
#define FF_DIM  4096
#define NK      (N_TOK * K_TOP)   // 16384 expanded rows
#define CHUNK   (NK / NE)         // 2048 rows per expert chunk

// Scratch (allocation-guard-safe __device__ globals)
__device__ float g_h[(size_t)NK * FF_DIM];  // 268 MB intermediate activations
__device__ int   g_expert[NK];
__device__ float g_wflat[NK];
__device__ int   g_rev[NK];
__device__ float g_sw[NK];

// ---------------------------------------------------------------------------
// Router: logits = x @ router_w^T, top-2, softmax over the 2 values.
// One warp per token; each lane accumulates partials for all 8 experts.
// ---------------------------------------------------------------------------
__global__ void router_kernel(const float* __restrict__ x,
                              const float* __restrict__ rw) {
    int gwarp = (blockIdx.x * blockDim.x + threadIdx.x) >> 5;
    int lane  = threadIdx.x & 31;
    if (gwarp >= N_TOK) return;
    const float* xr = x + (size_t)gwarp * D_MODEL;

    float acc[NE];
#pragma unroll
    for (int e = 0; e < NE; e++) acc[e] = 0.f;
    for (int c = lane; c < D_MODEL; c += 32) {
        float xv = xr[c];
#pragma unroll
        for (int e = 0; e < NE; e++) acc[e] += xv * rw[e * D_MODEL + c];
    }
#pragma unroll
    for (int e = 0; e < NE; e++) {
#pragma unroll
        for (int o = 16; o > 0; o >>= 1)
            acc[e] += __shfl_xor_sync(0xffffffffu, acc[e], o);
    }
    if (lane == 0) {
        // top-2 with jax.lax.top_k tie semantics (stable: lowest index first)
        int i0 = 0; float v0 = acc[0];
#pragma unroll
        for (int e = 1; e < NE; e++) { if (acc[e] > v0) { v0 = acc[e]; i0 = e; } }
        int i1 = -1; float v1 = -INFINITY;
#pragma unroll
        for (int e = 0; e < NE; e++) {
            if (e != i0 && acc[e] > v1) { v1 = acc[e]; i1 = e; }
        }
        float ex = expf(v1 - v0);          // v0 >= v1
        float inv = 1.f / (1.f + ex);
        g_expert[gwarp * 2 + 0] = i0;
        g_expert[gwarp * 2 + 1] = i1;
        g_wflat[gwarp * 2 + 0] = inv;
        g_wflat[gwarp * 2 + 1] = ex * inv;
    }
}

// ---------------------------------------------------------------------------
// Stable counting sort of 16384 (token,k) pairs by expert id.
// Single block, 256 threads, 64 consecutive elements each.
// Produces g_rev (token per sorted slot) and g_sw (gate weight per slot).
// ---------------------------------------------------------------------------
__global__ void sort_kernel() {
    __shared__ int cnt[256][NE];
    __shared__ int base[NE];
    int tid = threadIdx.x;
    int start = tid * 64;

    int my[NE];
#pragma unroll
    for (int e = 0; e < NE; e++) my[e] = 0;
    for (int j = 0; j < 64; j++) my[g_expert[start + j]]++;
#pragma unroll
    for (int e = 0; e < NE; e++) cnt[tid][e] = my[e];
    __syncthreads();

    if (tid < NE) {                 // per-expert exclusive scan across threads
        int e = tid, run = 0;
        for (int t = 0; t < 256; t++) { int c = cnt[t][e]; cnt[t][e] = run; run += c; }
        base[e] = run;              // total for expert e
    }
    __syncthreads();
    if (tid == 0) {                 // exclusive scan of expert totals
        int run = 0;
        for (int e = 0; e < NE; e++) { int c = base[e]; base[e] = run; run += c; }
    }
    __syncthreads();

    int off[NE];
#pragma unroll
    for (int e = 0; e < NE; e++) off[e] = base[e] + cnt[tid][e];
    for (int j = 0; j < 64; j++) {
        int i = start + j;
        int e = g_expert[i];
        int pos = off[e]++;
        g_rev[pos] = i >> 1;        // source token id
        g_sw[pos]  = g_wflat[i];
    }
}

// ---------------------------------------------------------------------------
// Tiled fp32 GEMMs: BM=BN=128, BK=16, 256 threads, 8x8 per-thread microtile.
// ---------------------------------------------------------------------------
#define BM 128
#define BN 128
#define BK 16
#define TM 8
#define TN 8

// GEMM1: h[e*C+m, nb+n] = gelu( sum_k x[rev[e*C+m], k] * w1[e, k, nb+n] )
__global__ __launch_bounds__(256) void gemm1_kernel(
    const float* __restrict__ x, const float* __restrict__ w1) {
    __shared__ float As[BK][BM];
    __shared__ float Bs[BK][BN];
    __shared__ int   srev[BM];

    int e  = blockIdx.z;
    int by = blockIdx.y;
    int bx = blockIdx.x;
    int tid = threadIdx.x;
    const float* w1e = w1 + (size_t)e * D_MODEL * FF_DIM;
    int srow0 = e * CHUNK + by * BM;
    if (tid < BM) srev[tid] = g_rev[srow0 + tid];
    __syncthreads();

    int tx = tid & 15, ty = tid >> 4;
    int nb = bx * BN;
    float acc[TM][TN];
#pragma unroll
    for (int i = 0; i < TM; i++)
#pragma unroll
        for (int j = 0; j < TN; j++) acc[i][j] = 0.f;

    for (int k0 = 0; k0 < D_MODEL; k0 += BK) {
#pragma unroll
        for (int jj = 0; jj < 2; jj++) {      // A: gather rows via srev
            int idx = tid + jj * 256;         // float4 slot 0..511
            int row = idx >> 2;
            int c4  = (idx & 3) * 4;
            float4 v = *(const float4*)(x + (size_t)srev[row] * D_MODEL + k0 + c4);
            As[c4 + 0][row] = v.x; As[c4 + 1][row] = v.y;
            As[c4 + 2][row] = v.z; As[c4 + 3][row] = v.w;
        }
#pragma unroll
        for (int jj = 0; jj < 2; jj++) {      // B: w1[e] rows, contiguous in n
            int idx = tid + jj * 256;
            int row = idx >> 5;
            int c4  = (idx & 31) * 4;
            *(float4*)&Bs[row][c4] =
                *(const float4*)(w1e + (size_t)(k0 + row) * FF_DIM + nb + c4);
        }
        __syncthreads();
#pragma unroll
        for (int k = 0; k < BK; k++) {
            float a[TM], b[TN];
#pragma unroll
            for (int i = 0; i < TM; i++) a[i] = As[k][ty * TM + i];
#pragma unroll
            for (int j = 0; j < TN; j++) b[j] = Bs[k][tx * TN + j];
#pragma unroll
            for (int i = 0; i < TM; i++)
#pragma unroll
                for (int j = 0; j < TN; j++) acc[i][j] += a[i] * b[j];
        }
        __syncthreads();
    }

    // Epilogue: exact GELU, store to g_h
#pragma unroll
    for (int i = 0; i < TM; i++) {
        int m = by * BM + ty * TM + i;
        float* hrow = g_h + (size_t)(e * CHUNK + m) * FF_DIM + nb + tx * TN;
#pragma unroll
        for (int j = 0; j < TN; j++) {
            float v = acc[i][j];
            hrow[j] = 0.5f * v * (1.f + erff(v * 0.70710678118654752f));
        }
    }
}

// GEMM2: y = h @ w2[e]; epilogue scales by gate weight and atomically
// scatter-adds into out[rev[row]].
__global__ __launch_bounds__(256) void gemm2_kernel(
    const float* __restrict__ w2, float* __restrict__ out) {
    __shared__ float As[BK][BM];
    __shared__ float Bs[BK][BN];

    int e  = blockIdx.z;
    int by = blockIdx.y;
    int bx = blockIdx.x;
    int tid = threadIdx.x;
    const float* w2e = w2 + (size_t)e * FF_DIM * D_MODEL;
    const float* Aep = g_h + (size_t)(e * CHUNK + by * BM) * FF_DIM;

    int tx = tid & 15, ty = tid >> 4;
    int nb = bx * BN;
    float acc[TM][TN];
#pragma unroll
    for (int i = 0; i < TM; i++)
#pragma unroll
        for (int j = 0; j < TN; j++) acc[i][j] = 0.f;

    for (int k0 = 0; k0 < FF_DIM; k0 += BK) {
#pragma unroll
        for (int jj = 0; jj < 2; jj++) {
            int idx = tid + jj * 256;
            int row = idx >> 2;
            int c4  = (idx & 3) * 4;
            float4 v = *(const float4*)(Aep + (size_t)row * FF_DIM + k0 + c4);
            As[c4 + 0][row] = v.x; As[c4 + 1][row] = v.y;
            As[c4 + 2][row] = v.z; As[c4 + 3][row] = v.w;
        }
#pragma unroll
        for (int jj = 0; jj < 2; jj++) {
            int idx = tid + jj * 256;
            int row = idx >> 5;
            int c4  = (idx & 31) * 4;
            *(float4*)&Bs[row][c4] =
                *(const float4*)(w2e + (size_t)(k0 + row) * D_MODEL + nb + c4);
        }
        __syncthreads();
#pragma unroll
        for (int k = 0; k < BK; k++) {
            float a[TM], b[TN];
#pragma unroll
            for (int i = 0; i < TM; i++) a[i] = As[k][ty * TM + i];
#pragma unroll
            for (int j = 0; j < TN; j++) b[j] = Bs[k][tx * TN + j];
#pragma unroll
            for (int i = 0; i < TM; i++)
#pragma unroll
                for (int j = 0; j < TN; j++) acc[i][j] += a[i] * b[j];
        }
        __syncthreads();
    }

    // Epilogue: gate-weight scale + scatter-add (each token gets exactly 2 adds)
#pragma unroll
    for (int i = 0; i < TM; i++) {
        int s = e * CHUNK + by * BM + ty * TM + i;
        float w = g_sw[s];
        int token = g_rev[s];
        float* orow = out + (size_t)token * D_MODEL + nb + tx * TN;
#pragma unroll
        for (int j = 0; j < TN; j++) atomicAdd(&orow[j], acc[i][j] * w);
    }
}

// Zero the (0xAA-poisoned) output before scatter-add.
__global__ void zero_kernel(float4* __restrict__ out, int n4) {
    int i = blockIdx.x * blockDim.x + threadIdx.x;
    if (i < n4) out[i] = make_float4(0.f, 0.f, 0.f, 0.f);
}

// ---------------------------------------------------------------------------
extern "C" void kernel_launch(void* const* d_in, const int* in_sizes, int n_in,
                              void* d_out, int out_size) {
    const float* x  = (const float*)d_in[0];   // [4,2048,1024]
    const float* rw = (const float*)d_in[1];   // [8,1024]
    const float* w1 = (const float*)d_in[2];   // [8,1024,4096]
    const float* w2 = (const float*)d_in[3];   // [8,4096,1024]
    float* out = (float*)d_out;                // [4,2048,1024]

    int n4 = (N_TOK * D_MODEL) / 4;
    zero_kernel<<<(n4 + 255) / 256, 256>>>((float4*)out, n4);
    router_kernel<<<N_TOK / 8, 256>>>(x, rw);
    sort_kernel<<<1, 256>>>();

    dim3 g1(FF_DIM / BN, CHUNK / BM, NE);      // 32 x 16 x 8
    gemm1_kernel<<<g1, 256>>>(x, w1);
    dim3 g2(D_MODEL / BN, CHUNK / BM, NE);     // 8 x 16 x 8
    gemm2_kernel<<<g2, 256>>>(w2, out);
}

// round 3
// speedup vs baseline: 2.7490x; 2.7490x over previous
#include <cuda_runtime.h>
#include <math.h>
#include <stdint.h>

// Problem constants (B=4, T=2048, D=1024, FF=4096, E=8, K=2)
#define N_TOK   8192
#define NE      8
#define D_MODEL 1024
#define FF_DIM  4096
#define NK      16384            // N_TOK * 2 expanded rows
#define CHUNK   2048             // NK / NE rows per expert chunk

// Scratch (__device__ globals: allocation-guard-safe)
__device__ float g_h[(size_t)NK * FF_DIM];   // 268 MB intermediate activations
__device__ float g_y[(size_t)NK * D_MODEL];  // 64 MB expert outputs (scaled)
__device__ int   g_expert[NK];
__device__ float g_wflat[NK];
__device__ int   g_rev[NK];
__device__ float g_sw[NK];
__device__ int   g_pos[NK];                  // inverse permutation

// ---------------------------------------------------------------------------
// fp32 -> tf32 with round-to-nearest (bias-free; mandatory for accuracy)
__device__ __forceinline__ uint32_t f2tf(float f) {
    uint32_t r;
    asm("cvt.rna.tf32.f32 %0, %1;" : "=r"(r) : "f"(f));
    return r;
}

// m16n8k8 tf32 HMMA (baseline PTX, works on compute_103)
__device__ __forceinline__ void mma16n8k8(float* d, const uint32_t* a,
                                          const uint32_t* b) {
    asm volatile(
        "mma.sync.aligned.m16n8k8.row.col.f32.tf32.tf32.f32 "
        "{%0,%1,%2,%3}, {%4,%5,%6,%7}, {%8,%9}, {%0,%1,%2,%3};"
        : "+f"(d[0]), "+f"(d[1]), "+f"(d[2]), "+f"(d[3])
        : "r"(a[0]), "r"(a[1]), "r"(a[2]), "r"(a[3]), "r"(b[0]), "r"(b[1]));
}

__device__ __forceinline__ float gelu_exact(float v) {
    return 0.5f * v * (1.f + erff(v * 0.70710678118654752f));
}

// ---------------------------------------------------------------------------
// Router (fp32, exact): logits, top-2, softmax-of-2. One warp per token.
// ---------------------------------------------------------------------------
__global__ void router_kernel(const float* __restrict__ x,
                              const float* __restrict__ rw) {
    int gwarp = (blockIdx.x * blockDim.x + threadIdx.x) >> 5;
    int lane  = threadIdx.x & 31;
    if (gwarp >= N_TOK) return;
    const float* xr = x + (size_t)gwarp * D_MODEL;
    float acc[NE];
#pragma unroll
    for (int e = 0; e < NE; e++) acc[e] = 0.f;
    for (int c = lane; c < D_MODEL; c += 32) {
        float xv = xr[c];
#pragma unroll
        for (int e = 0; e < NE; e++) acc[e] += xv * rw[e * D_MODEL + c];
    }
#pragma unroll
    for (int e = 0; e < NE; e++)
#pragma unroll
        for (int o = 16; o > 0; o >>= 1)
            acc[e] += __shfl_xor_sync(0xffffffffu, acc[e], o);
    if (lane == 0) {
        int i0 = 0; float v0 = acc[0];
#pragma unroll
        for (int e = 1; e < NE; e++) if (acc[e] > v0) { v0 = acc[e]; i0 = e; }
        int i1 = -1; float v1 = -INFINITY;
#pragma unroll
        for (int e = 0; e < NE; e++)
            if (e != i0 && acc[e] > v1) { v1 = acc[e]; i1 = e; }
        float ex = expf(v1 - v0);
        float inv = 1.f / (1.f + ex);
        g_expert[gwarp * 2 + 0] = i0;
        g_expert[gwarp * 2 + 1] = i1;
        g_wflat[gwarp * 2 + 0] = inv;
        g_wflat[gwarp * 2 + 1] = ex * inv;
    }
}

// ---------------------------------------------------------------------------
// Stable counting sort by expert id; also emits inverse permutation g_pos.
// ---------------------------------------------------------------------------
__global__ void sort_kernel() {
    __shared__ int cnt[256][NE];
    __shared__ int base[NE];
    int tid = threadIdx.x;
    int start = tid * 64;
    int my[NE];
#pragma unroll
    for (int e = 0; e < NE; e++) my[e] = 0;
    for (int j = 0; j < 64; j++) my[g_expert[start + j]]++;
#pragma unroll
    for (int e = 0; e < NE; e++) cnt[tid][e] = my[e];
    __syncthreads();
    if (tid < NE) {
        int e = tid, run = 0;
        for (int t = 0; t < 256; t++) { int c = cnt[t][e]; cnt[t][e] = run; run += c; }
        base[e] = run;
    }
    __syncthreads();
    if (tid == 0) {
        int run = 0;
        for (int e = 0; e < NE; e++) { int c = base[e]; base[e] = run; run += c; }
    }
    __syncthreads();
    int off[NE];
#pragma unroll
    for (int e = 0; e < NE; e++) off[e] = base[e] + cnt[tid][e];
    for (int j = 0; j < 64; j++) {
        int i = start + j;
        int e = g_expert[i];
        int pos = off[e]++;
        g_rev[pos] = i >> 1;
        g_sw[pos]  = g_wflat[i];
        g_pos[i]   = pos;
    }
}

// ---------------------------------------------------------------------------
// tf32 mma.sync GEMMs: BM=BN=128, BK=32, 256 threads (8 warps, 4x2),
// warp tile 32(M) x 64(N) = 2 m-frags x 8 n-frags of m16n8k8.
// Smem pitches: A 36 floats, B 136 floats (conflict-free fragment LDS).
// ---------------------------------------------------------------------------
#define BM 128
#define BN 128
#define BKF 32
#define PA 36
#define PB 136

// GEMM1: h = gelu( gather(x, rev) @ w1[e] )   [A gathered, K=1024]
__global__ __launch_bounds__(256) void gemm1_mma(const float* __restrict__ x,
                                                 const float* __restrict__ w1) {
    __shared__ uint32_t As[BM * PA];
    __shared__ uint32_t Bs[BKF * PB];
    __shared__ int srev[BM];

    int tid = threadIdx.x, lane = tid & 31, wid = tid >> 5;
    int mt = blockIdx.x, ntb = blockIdx.y, e = blockIdx.z;
    const float* w1e = w1 + (size_t)e * D_MODEL * FF_DIM;
    int nb = ntb * BN;
    if (tid < BM) srev[tid] = g_rev[e * CHUNK + mt * BM + tid];
    __syncthreads();

    int wm = wid & 3, wn = wid >> 2;           // warp coords: 4 in M, 2 in N
    float acc[2][8][4];
#pragma unroll
    for (int i = 0; i < 2; i++)
#pragma unroll
        for (int j = 0; j < 8; j++)
#pragma unroll
            for (int c = 0; c < 4; c++) acc[i][j][c] = 0.f;

    for (int k0 = 0; k0 < D_MODEL; k0 += BKF) {
        // Load A: 128 rows x 8 float4 (gather via srev), tf32-round into smem
#pragma unroll
        for (int j = 0; j < 4; j++) {
            int idx = tid + j * 256;           // 0..1023
            int row = idx >> 3, c4 = (idx & 7) << 2;
            float4 v = *(const float4*)(x + (size_t)srev[row] * D_MODEL + k0 + c4);
            uint32_t* p = &As[row * PA + c4];
            p[0] = f2tf(v.x); p[1] = f2tf(v.y); p[2] = f2tf(v.z); p[3] = f2tf(v.w);
        }
        // Load B: 32 k-rows x 32 float4 (coalesced in n)
#pragma unroll
        for (int j = 0; j < 4; j++) {
            int idx = tid + j * 256;
            int k = idx >> 5, c4 = (idx & 31) << 2;
            float4 v = *(const float4*)(w1e + (size_t)(k0 + k) * FF_DIM + nb + c4);
            uint32_t* p = &Bs[k * PB + c4];
            p[0] = f2tf(v.x); p[1] = f2tf(v.y); p[2] = f2tf(v.z); p[3] = f2tf(v.w);
        }
        __syncthreads();
#pragma unroll
        for (int k8 = 0; k8 < 4; k8++) {
            uint32_t a[2][4];
#pragma unroll
            for (int m2 = 0; m2 < 2; m2++) {
                int rb = wm * 32 + m2 * 16 + (lane >> 2);
                int c = k8 * 8 + (lane & 3);
                a[m2][0] = As[rb * PA + c];
                a[m2][1] = As[(rb + 8) * PA + c];
                a[m2][2] = As[rb * PA + c + 4];
                a[m2][3] = As[(rb + 8) * PA + c + 4];
            }
            uint32_t b[8][2];
#pragma unroll
            for (int n2 = 0; n2 < 8; n2++) {
                int n = wn * 64 + n2 * 8 + (lane >> 2);
                int k = k8 * 8 + (lane & 3);
                b[n2][0] = Bs[k * PB + n];
                b[n2][1] = Bs[(k + 4) * PB + n];
            }
#pragma unroll
            for (int m2 = 0; m2 < 2; m2++)
#pragma unroll
                for (int n2 = 0; n2 < 8; n2++)
                    mma16n8k8(acc[m2][n2], a[m2], b[n2]);
        }
        __syncthreads();
    }

    // Epilogue: GELU -> g_h
    int hrow0 = e * CHUNK + mt * BM;
#pragma unroll
    for (int m2 = 0; m2 < 2; m2++) {
        int r0 = wm * 32 + m2 * 16 + (lane >> 2);
#pragma unroll
        for (int half = 0; half < 2; half++) {
            float* hr = g_h + (size_t)(hrow0 + r0 + half * 8) * FF_DIM + nb;
#pragma unroll
            for (int n2 = 0; n2 < 8; n2++) {
                int col = wn * 64 + n2 * 8 + 2 * (lane & 3);
                float2 o;
                o.x = gelu_exact(acc[m2][n2][half * 2 + 0]);
                o.y = gelu_exact(acc[m2][n2][half * 2 + 1]);
                *(float2*)(hr + col) = o;
            }
        }
    }
}

// GEMM2: y = (h @ w2[e]) * sw   [A contiguous, K=4096]
__global__ __launch_bounds__(256) void gemm2_mma(const float* __restrict__ w2) {
    __shared__ uint32_t As[BM * PA];
    __shared__ uint32_t Bs[BKF * PB];

    int tid = threadIdx.x, lane = tid & 31, wid = tid >> 5;
    int mt = blockIdx.x, ntb = blockIdx.y, e = blockIdx.z;
    const float* w2e = w2 + (size_t)e * FF_DIM * D_MODEL;
    const float* Aep = g_h + (size_t)(e * CHUNK + mt * BM) * FF_DIM;
    int nb = ntb * BN;

    int wm = wid & 3, wn = wid >> 2;
    float acc[2][8][4];
#pragma unroll
    for (int i = 0; i < 2; i++)
#pragma unroll
        for (int j = 0; j < 8; j++)
#pragma unroll
            for (int c = 0; c < 4; c++) acc[i][j][c] = 0.f;

    for (int k0 = 0; k0 < FF_DIM; k0 += BKF) {
#pragma unroll
        for (int j = 0; j < 4; j++) {
            int idx = tid + j * 256;
            int row = idx >> 3, c4 = (idx & 7) << 2;
            float4 v = *(const float4*)(Aep + (size_t)row * FF_DIM + k0 + c4);
            uint32_t* p = &As[row * PA + c4];
            p[0] = f2tf(v.x); p[1] = f2tf(v.y); p[2] = f2tf(v.z); p[3] = f2tf(v.w);
        }
#pragma unroll
        for (int j = 0; j < 4; j++) {
            int idx = tid + j * 256;
            int k = idx >> 5, c4 = (idx & 31) << 2;
            float4 v = *(const float4*)(w2e + (size_t)(k0 + k) * D_MODEL + nb + c4);
            uint32_t* p = &Bs[k * PB + c4];
            p[0] = f2tf(v.x); p[1] = f2tf(v.y); p[2] = f2tf(v.z); p[3] = f2tf(v.w);
        }
        __syncthreads();
#pragma unroll
        for (int k8 = 0; k8 < 4; k8++) {
            uint32_t a[2][4];
#pragma unroll
            for (int m2 = 0; m2 < 2; m2++) {
                int rb = wm * 32 + m2 * 16 + (lane >> 2);
                int c = k8 * 8 + (lane & 3);
                a[m2][0] = As[rb * PA + c];
                a[m2][1] = As[(rb + 8) * PA + c];
                a[m2][2] = As[rb * PA + c + 4];
                a[m2][3] = As[(rb + 8) * PA + c + 4];
            }
            uint32_t b[8][2];
#pragma unroll
            for (int n2 = 0; n2 < 8; n2++) {
                int n = wn * 64 + n2 * 8 + (lane >> 2);
                int k = k8 * 8 + (lane & 3);
                b[n2][0] = Bs[k * PB + n];
                b[n2][1] = Bs[(k + 4) * PB + n];
            }
#pragma unroll
            for (int m2 = 0; m2 < 2; m2++)
#pragma unroll
                for (int n2 = 0; n2 < 8; n2++)
                    mma16n8k8(acc[m2][n2], a[m2], b[n2]);
        }
        __syncthreads();
    }

    // Epilogue: gate-weight scale -> g_y (sorted order)
    int srow0 = e * CHUNK + mt * BM;
#pragma unroll
    for (int m2 = 0; m2 < 2; m2++) {
        int r0 = wm * 32 + m2 * 16 + (lane >> 2);
#pragma unroll
        for (int half = 0; half < 2; half++) {
            int srow = srow0 + r0 + half * 8;
            float w = g_sw[srow];
            float* yr = g_y + (size_t)srow * D_MODEL + nb;
#pragma unroll
            for (int n2 = 0; n2 < 8; n2++) {
                int col = wn * 64 + n2 * 8 + 2 * (lane & 3);
                float2 o;
                o.x = acc[m2][n2][half * 2 + 0] * w;
                o.y = acc[m2][n2][half * 2 + 1] * w;
                *(float2*)(yr + col) = o;
            }
        }
    }
}

// Combine: out[t] = y[pos(t,0)] + y[pos(t,1)]  (full overwrite, no atomics)
__global__ void combine_kernel(float* __restrict__ out) {
    int t = blockIdx.x;
    int c = threadIdx.x * 4;
    int p0 = g_pos[2 * t], p1 = g_pos[2 * t + 1];
    float4 a = *(const float4*)(g_y + (size_t)p0 * D_MODEL + c);
    float4 b = *(const float4*)(g_y + (size_t)p1 * D_MODEL + c);
    float4 o;
    o.x = a.x + b.x; o.y = a.y + b.y; o.z = a.z + b.z; o.w = a.w + b.w;
    *(float4*)(out + (size_t)t * D_MODEL + c) = o;
}

// ---------------------------------------------------------------------------
extern "C" void kernel_launch(void* const* d_in, const int* in_sizes, int n_in,
                              void* d_out, int out_size) {
    const float* x  = (const float*)d_in[0];   // [4,2048,1024]
    const float* rw = (const float*)d_in[1];   // [8,1024]
    const float* w1 = (const float*)d_in[2];   // [8,1024,4096]
    const float* w2 = (const float*)d_in[3];   // [8,4096,1024]
    float* out = (float*)d_out;                // [4,2048,1024]

    router_kernel<<<N_TOK / 8, 256>>>(x, rw);
    sort_kernel<<<1, 256>>>();

    dim3 g1(CHUNK / BM, FF_DIM / BN, NE);      // 16 x 32 x 8
    gemm1_mma<<<g1, 256>>>(x, w1);
    dim3 g2(CHUNK / BM, D_MODEL / BN, NE);     // 16 x 8 x 8
    gemm2_mma<<<g2, 256>>>(w2);

    combine_kernel<<<N_TOK, 256>>>(out);
}

// round 5
// speedup vs baseline: 3.5980x; 1.3088x over previous
#include <cuda_runtime.h>
#include <math.h>
#include <stdint.h>

// Problem constants (B=4, T=2048, D=1024, FF=4096, E=8, K=2)
#define N_TOK   8192
#define NE      8
#define D_MODEL 1024
#define FF_DIM  4096
#define NK      16384            // N_TOK * 2 expanded rows
#define CHUNK   2048             // NK / NE rows per expert chunk

// Scratch (__device__ globals: allocation-guard-safe)
__device__ float g_h[(size_t)NK * FF_DIM];   // 268 MB intermediate activations
__device__ float g_y[(size_t)NK * D_MODEL];  // 64 MB expert outputs (scaled)
__device__ int   g_expert[NK];
__device__ float g_wflat[NK];
__device__ int   g_rev[NK];
__device__ float g_sw[NK];
__device__ int   g_pos[NK];                  // inverse permutation

// ---------------------------------------------------------------------------
// fp32 -> tf32 round-to-nearest (bias-free; mandatory for accuracy)
__device__ __forceinline__ uint32_t f2tf(float f) {
    uint32_t r;
    asm("cvt.rna.tf32.f32 %0, %1;" : "=r"(r) : "f"(f));
    return r;
}
__device__ __forceinline__ uint32_t f2tf_u(uint32_t raw) {
    return f2tf(__uint_as_float(raw));
}

// m16n8k8 tf32 HMMA (baseline PTX, works on compute_103)
__device__ __forceinline__ void mma16n8k8(float* d, const uint32_t* a,
                                          const uint32_t* b) {
    asm volatile(
        "mma.sync.aligned.m16n8k8.row.col.f32.tf32.tf32.f32 "
        "{%0,%1,%2,%3}, {%4,%5,%6,%7}, {%8,%9}, {%0,%1,%2,%3};"
        : "+f"(d[0]), "+f"(d[1]), "+f"(d[2]), "+f"(d[3])
        : "r"(a[0]), "r"(a[1]), "r"(a[2]), "r"(a[3]), "r"(b[0]), "r"(b[1]));
}

// cp.async (sm_80 baseline)
__device__ __forceinline__ void cp16(uint32_t dst, const void* src) {
    asm volatile("cp.async.cg.shared.global [%0], [%1], 16;"
                 :: "r"(dst), "l"(src));
}
#define CP_COMMIT() asm volatile("cp.async.commit_group;" ::: "memory")
#define CP_WAIT(n)  asm volatile("cp.async.wait_group %0;" :: "n"(n) : "memory")

__device__ __forceinline__ float gelu_exact(float v) {
    return 0.5f * v * (1.f + erff(v * 0.70710678118654752f));
}

// ---------------------------------------------------------------------------
// Router (fp32, exact): logits, top-2, softmax-of-2. One warp per token.
// ---------------------------------------------------------------------------
__global__ void router_kernel(const float* __restrict__ x,
                              const float* __restrict__ rw) {
    int gwarp = (blockIdx.x * blockDim.x + threadIdx.x) >> 5;
    int lane  = threadIdx.x & 31;
    if (gwarp >= N_TOK) return;
    const float* xr = x + (size_t)gwarp * D_MODEL;
    float acc[NE];
#pragma unroll
    for (int e = 0; e < NE; e++) acc[e] = 0.f;
    for (int c = lane; c < D_MODEL; c += 32) {
        float xv = xr[c];
#pragma unroll
        for (int e = 0; e < NE; e++) acc[e] += xv * rw[e * D_MODEL + c];
    }
#pragma unroll
    for (int e = 0; e < NE; e++)
#pragma unroll
        for (int o = 16; o > 0; o >>= 1)
            acc[e] += __shfl_xor_sync(0xffffffffu, acc[e], o);
    if (lane == 0) {
        int i0 = 0; float v0 = acc[0];
#pragma unroll
        for (int e = 1; e < NE; e++) if (acc[e] > v0) { v0 = acc[e]; i0 = e; }
        int i1 = -1; float v1 = -INFINITY;
#pragma unroll
        for (int e = 0; e < NE; e++)
            if (e != i0 && acc[e] > v1) { v1 = acc[e]; i1 = e; }
        float ex = expf(v1 - v0);
        float inv = 1.f / (1.f + ex);
        g_expert[gwarp * 2 + 0] = i0;
        g_expert[gwarp * 2 + 1] = i1;
        g_wflat[gwarp * 2 + 0] = inv;
        g_wflat[gwarp * 2 + 1] = ex * inv;
    }
}

// ---------------------------------------------------------------------------
// Stable counting sort by expert id; also emits inverse permutation g_pos.
// ---------------------------------------------------------------------------
__global__ void sort_kernel() {
    __shared__ int cnt[256][NE];
    __shared__ int base[NE];
    int tid = threadIdx.x;
    int start = tid * 64;
    int my[NE];
#pragma unroll
    for (int e = 0; e < NE; e++) my[e] = 0;
    for (int j = 0; j < 64; j++) my[g_expert[start + j]]++;
#pragma unroll
    for (int e = 0; e < NE; e++) cnt[tid][e] = my[e];
    __syncthreads();
    if (tid < NE) {
        int e = tid, run = 0;
        for (int t = 0; t < 256; t++) { int c = cnt[t][e]; cnt[t][e] = run; run += c; }
        base[e] = run;
    }
    __syncthreads();
    if (tid == 0) {
        int run = 0;
        for (int e = 0; e < NE; e++) { int c = base[e]; base[e] = run; run += c; }
    }
    __syncthreads();
    int off[NE];
#pragma unroll
    for (int e = 0; e < NE; e++) off[e] = base[e] + cnt[tid][e];
    for (int j = 0; j < 64; j++) {
        int i = start + j;
        int e = g_expert[i];
        int pos = off[e]++;
        g_rev[pos] = i >> 1;
        g_sw[pos]  = g_wflat[i];
        g_pos[i]   = pos;
    }
}

// ---------------------------------------------------------------------------
// tf32 mma.sync GEMMs with cp.async double buffering.
// BM=BN=128, BK=32 floats, 256 threads (8 warps, 4x2), warp tile 32x64.
// Smem holds RAW fp32 (cp.async); tf32 RN conversion at fragment load.
// Pitches: A 36, B 136 floats (conflict-free fragment LDS).
// ---------------------------------------------------------------------------
#define BM 128
#define BN 128
#define BKF 32
#define PA 36
#define PB 136
#define A_BUF (BM * PA)                  // 4608 u32
#define B_BUF (BKF * PB)                 // 4352 u32
#define SMEM_U32 (2 * A_BUF + 2 * B_BUF + 128)
#define SMEM_BYTES (SMEM_U32 * 4)        // 72192 B

// Issue cp.async loads for one stage. arow_base: per-row gmem row pointers via
// srev (gemm1) or nullptr for contiguous A (gemm2).
template <bool GATHER>
__device__ __forceinline__ void issue_stage(
    uint32_t sA, uint32_t sB, const float* __restrict__ Abase,
    const int* __restrict__ srev, size_t lda,
    const float* __restrict__ Bsrc, size_t ldb, int tid) {
#pragma unroll
    for (int j = 0; j < 4; j++) {
        int idx = tid + j * 256;               // 0..1023
        int row = idx >> 3, c4 = (idx & 7) << 2;
        const float* src = GATHER
            ? Abase + (size_t)srev[row] * lda + c4
            : Abase + (size_t)row * lda + c4;
        cp16(sA + (uint32_t)(row * PA + c4) * 4, src);
    }
#pragma unroll
    for (int j = 0; j < 4; j++) {
        int idx = tid + j * 256;
        int k = idx >> 5, c4 = (idx & 31) << 2;
        cp16(sB + (uint32_t)(k * PB + c4) * 4, Bsrc + (size_t)k * ldb + c4);
    }
}

// Core compute on one smem stage: 4 k8 steps, 16 HMMA each.
__device__ __forceinline__ void compute_stage(
    const uint32_t* __restrict__ As, const uint32_t* __restrict__ Bs,
    int lane, int wm, int wn, float acc[2][8][4]) {
#pragma unroll
    for (int k8 = 0; k8 < 4; k8++) {
        uint32_t a[2][4];
#pragma unroll
        for (int m2 = 0; m2 < 2; m2++) {
            int rb = wm * 32 + m2 * 16 + (lane >> 2);
            int c = k8 * 8 + (lane & 3);
            a[m2][0] = f2tf_u(As[rb * PA + c]);
            a[m2][1] = f2tf_u(As[(rb + 8) * PA + c]);
            a[m2][2] = f2tf_u(As[rb * PA + c + 4]);
            a[m2][3] = f2tf_u(As[(rb + 8) * PA + c + 4]);
        }
        uint32_t b[8][2];
#pragma unroll
        for (int n2 = 0; n2 < 8; n2++) {
            int n = wn * 64 + n2 * 8 + (lane >> 2);
            int k = k8 * 8 + (lane & 3);
            b[n2][0] = f2tf_u(Bs[k * PB + n]);
            b[n2][1] = f2tf_u(Bs[(k + 4) * PB + n]);
        }
#pragma unroll
        for (int m2 = 0; m2 < 2; m2++)
#pragma unroll
            for (int n2 = 0; n2 < 8; n2++)
                mma16n8k8(acc[m2][n2], a[m2], b[n2]);
    }
}

// GEMM1: h = gelu( gather(x, rev) @ w1[e] )   [K=1024, 32 stages]
__global__ __launch_bounds__(256, 2) void gemm1_mma(
    const float* __restrict__ x, const float* __restrict__ w1) {
    extern __shared__ uint32_t smem[];
    uint32_t* As = smem;
    uint32_t* Bs = smem + 2 * A_BUF;
    int* srev = (int*)(smem + 2 * A_BUF + 2 * B_BUF);
    uint32_t sbase = (uint32_t)__cvta_generic_to_shared(smem);
    uint32_t sA = sbase, sB = sbase + 2 * A_BUF * 4;

    int tid = threadIdx.x, lane = tid & 31, wid = tid >> 5;
    int mt = blockIdx.x, ntb = blockIdx.y, e = blockIdx.z;
    const float* w1e = w1 + (size_t)e * D_MODEL * FF_DIM;
    int nb = ntb * BN;
    if (tid < BM) srev[tid] = g_rev[e * CHUNK + mt * BM + tid];
    __syncthreads();

    int wm = wid & 3, wn = wid >> 2;
    float acc[2][8][4];
#pragma unroll
    for (int i = 0; i < 2; i++)
#pragma unroll
        for (int j = 0; j < 8; j++)
#pragma unroll
            for (int c = 0; c < 4; c++) acc[i][j][c] = 0.f;

    const int S = D_MODEL / BKF;   // 32
    issue_stage<true>(sA, sB, x, srev, D_MODEL, w1e + nb, FF_DIM, tid);
    CP_COMMIT();
    for (int s = 0; s < S; s++) {
        int buf = s & 1, nxt = buf ^ 1;
        if (s + 1 < S) {
            int k0 = (s + 1) * BKF;
            issue_stage<true>(sA + nxt * A_BUF * 4, sB + nxt * B_BUF * 4,
                              x + k0, srev, D_MODEL,
                              w1e + (size_t)k0 * FF_DIM + nb, FF_DIM, tid);
            CP_COMMIT();
            CP_WAIT(1);
        } else {
            CP_WAIT(0);
        }
        __syncthreads();
        compute_stage(As + buf * A_BUF, Bs + buf * B_BUF, lane, wm, wn, acc);
        __syncthreads();
    }

    // Epilogue: GELU -> g_h
    int hrow0 = e * CHUNK + mt * BM;
#pragma unroll
    for (int m2 = 0; m2 < 2; m2++) {
        int r0 = wm * 32 + m2 * 16 + (lane >> 2);
#pragma unroll
        for (int half = 0; half < 2; half++) {
            float* hr = g_h + (size_t)(hrow0 + r0 + half * 8) * FF_DIM + nb;
#pragma unroll
            for (int n2 = 0; n2 < 8; n2++) {
                int col = wn * 64 + n2 * 8 + 2 * (lane & 3);
                float2 o;
                o.x = gelu_exact(acc[m2][n2][half * 2 + 0]);
                o.y = gelu_exact(acc[m2][n2][half * 2 + 1]);
                *(float2*)(hr + col) = o;
            }
        }
    }
}

// GEMM2: y = (h @ w2[e]) * sw   [K=4096, 128 stages]
__global__ __launch_bounds__(256, 2) void gemm2_mma(const float* __restrict__ w2) {
    extern __shared__ uint32_t smem[];
    uint32_t* As = smem;
    uint32_t* Bs = smem + 2 * A_BUF;
    uint32_t sbase = (uint32_t)__cvta_generic_to_shared(smem);
    uint32_t sA = sbase, sB = sbase + 2 * A_BUF * 4;

    int tid = threadIdx.x, lane = tid & 31, wid = tid >> 5;
    int mt = blockIdx.x, ntb = blockIdx.y, e = blockIdx.z;
    const float* w2e = w2 + (size_t)e * FF_DIM * D_MODEL;
    const float* Aep = g_h + (size_t)(e * CHUNK + mt * BM) * FF_DIM;
    int nb = ntb * BN;

    int wm = wid & 3, wn = wid >> 2;
    float acc[2][8][4];
#pragma unroll
    for (int i = 0; i < 2; i++)
#pragma unroll
        for (int j = 0; j < 8; j++)
#pragma unroll
            for (int c = 0; c < 4; c++) acc[i][j][c] = 0.f;

    const int S = FF_DIM / BKF;    // 128
    issue_stage<false>(sA, sB, Aep, nullptr, FF_DIM, w2e + nb, D_MODEL, tid);
    CP_COMMIT();
    for (int s = 0; s < S; s++) {
        int buf = s & 1, nxt = buf ^ 1;
        if (s + 1 < S) {
            int k0 = (s + 1) * BKF;
            issue_stage<false>(sA + nxt * A_BUF * 4, sB + nxt * B_BUF * 4,
                               Aep + k0, nullptr, FF_DIM,
                               w2e + (size_t)k0 * D_MODEL + nb, D_MODEL, tid);
            CP_COMMIT();
            CP_WAIT(1);
        } else {
            CP_WAIT(0);
        }
        __syncthreads();
        compute_stage(As + buf * A_BUF, Bs + buf * B_BUF, lane, wm, wn, acc);
        __syncthreads();
    }

    // Epilogue: gate-weight scale -> g_y (sorted order)
    int srow0 = e * CHUNK + mt * BM;
#pragma unroll
    for (int m2 = 0; m2 < 2; m2++) {
        int r0 = wm * 32 + m2 * 16 + (lane >> 2);
#pragma unroll
        for (int half = 0; half < 2; half++) {
            int srow = srow0 + r0 + half * 8;
            float w = g_sw[srow];
            float* yr = g_y + (size_t)srow * D_MODEL + nb;
#pragma unroll
            for (int n2 = 0; n2 < 8; n2++) {
                int col = wn * 64 + n2 * 8 + 2 * (lane & 3);
                float2 o;
                o.x = acc[m2][n2][half * 2 + 0] * w;
                o.y = acc[m2][n2][half * 2 + 1] * w;
                *(float2*)(yr + col) = o;
            }
        }
    }
}

// Combine: out[t] = y[pos(t,0)] + y[pos(t,1)]  (full overwrite, no atomics)
__global__ void combine_kernel(float* __restrict__ out) {
    int t = blockIdx.x;
    int c = threadIdx.x * 4;
    int p0 = g_pos[2 * t], p1 = g_pos[2 * t + 1];
    float4 a = *(const float4*)(g_y + (size_t)p0 * D_MODEL + c);
    float4 b = *(const float4*)(g_y + (size_t)p1 * D_MODEL + c);
    float4 o;
    o.x = a.x + b.x; o.y = a.y + b.y; o.z = a.z + b.z; o.w = a.w + b.w;
    *(float4*)(out + (size_t)t * D_MODEL + c) = o;
}

// ---------------------------------------------------------------------------
extern "C" void kernel_launch(void* const* d_in, const int* in_sizes, int n_in,
                              void* d_out, int out_size) {
    const float* x  = (const float*)d_in[0];   // [4,2048,1024]
    const float* rw = (const float*)d_in[1];   // [8,1024]
    const float* w1 = (const float*)d_in[2];   // [8,1024,4096]
    const float* w2 = (const float*)d_in[3];   // [8,4096,1024]
    float* out = (float*)d_out;                // [4,2048,1024]

    static int attr_done = 0;
    if (!attr_done) {
        cudaFuncSetAttribute(gemm1_mma,
            cudaFuncAttributeMaxDynamicSharedMemorySize, SMEM_BYTES);
        cudaFuncSetAttribute(gemm2_mma,
            cudaFuncAttributeMaxDynamicSharedMemorySize, SMEM_BYTES);
        attr_done = 1;
    }

    router_kernel<<<N_TOK / 8, 256>>>(x, rw);
    sort_kernel<<<1, 256>>>();

    dim3 g1(CHUNK / BM, FF_DIM / BN, NE);      // 16 x 32 x 8
    gemm1_mma<<<g1, 256, SMEM_BYTES>>>(x, w1);
    dim3 g2(CHUNK / BM, D_MODEL / BN, NE);     // 16 x 8 x 8
    gemm2_mma<<<g2, 256, SMEM_BYTES>>>(w2);

    combine_kernel<<<N_TOK, 256>>>(out);
}